// round 15
// baseline (speedup 1.0000x reference)
#include <cuda_runtime.h>
#include <cuda_bf16.h>

#define Bn 4
#define Sn 4096
#define Hn 2048
#define H4 (Hn / 4)
#define EPSf 1e-6f

#define CS 16               // output rows per block
#define CHK 4               // rows per pipeline chunk
#define NCHK (CS / CHK)     // 4
#define NPRO 7              // prologue rows: 3 halo + chunk 0
#define NQP (NPRO * 4)      // 28 prologue quarter-rows

__device__ __forceinline__ float warp_sum(float v) {
#pragma unroll
    for (int o = 16; o; o >>= 1)
        v += __shfl_xor_sync(0xFFFFFFFFu, v, o);
    return v;
}

__device__ __forceinline__ float dot4(const float4 v) {
    return fmaf(v.x, v.x, fmaf(v.y, v.y, fmaf(v.z, v.z, v.w * v.w)));
}

// ---------------------------------------------------------------------------
// Fused RMSNorm + depthwise causal conv1d (K=4) + bias, software-pipelined.
// grid = (S/CS, B) = 1024 blocks, block = 512, occ 2. Same traffic as R3.
// Pipeline: each iteration issues the NEXT chunk's DRAM quarter-row loads
// (4 LDG.128/warp, kept in scoreboard), convolves+stores the CURRENT chunk,
// then consumes the loads into the rmsnorm reduction. DRAM reads thus stay
// in flight through the conv/store section -> higher DRAM duty cycle.
// ---------------------------------------------------------------------------
__global__ __launch_bounds__(512, 2) void fused_kernel(const float* __restrict__ x,
                                                       const float* __restrict__ nw,
                                                       const float* __restrict__ cw,
                                                       const float* __restrict__ cb,
                                                       float*       __restrict__ out) {
    __shared__ float s_part[NQP];        // quarter-row partial sums (reused)
    __shared__ float s_ir[CS + 3];       // per-window-row inv_rms

    const int b    = blockIdx.y;
    const int s0   = blockIdx.x * CS;
    const int tid  = threadIdx.x;
    const int warp = tid >> 5;
    const int lane = tid & 31;

    const float* xb = x   + (size_t)b * Sn * Hn;
    float*       ob = out + (size_t)b * Sn * Hn;

    // ---- per-thread constants (issued first; independent of everything) ----
    const int h4 = tid;
    const int h  = h4 * 4;
    const float4* cw4 = reinterpret_cast<const float4*>(cw);
    const float4 nwv = __ldg(&reinterpret_cast<const float4*>(nw)[h4]);
    float4 t0 = __ldg(&cw4[h + 0]);
    float4 t1 = __ldg(&cw4[h + 1]);
    float4 t2 = __ldg(&cw4[h + 2]);
    float4 t3 = __ldg(&cw4[h + 3]);
    const float4 bias = __ldg(&reinterpret_cast<const float4*>(cb)[h4]);

    // ---- prologue: reduce rows s0-3 .. s0+3 (28 quarter-rows, 2 per warp) ----
    {
        const int q1 = warp;          // 0..15
        const int q2 = warp + 16;     // 16..31, valid if < 28
        const int j1 = q1 >> 2, k1 = q1 & 3, s1 = s0 - 3 + j1;
        const int j2 = q2 >> 2, k2 = q2 & 3, s2 = s0 - 3 + j2;

        float a1 = 0.f, a2 = 0.f;
        if (s1 >= 0) {
            const float4* r1 = reinterpret_cast<const float4*>(xb + (size_t)s1 * Hn) + k1 * 128;
            float4 u0 = r1[lane + 0];
            float4 u1 = r1[lane + 32];
            float4 u2 = r1[lane + 64];
            float4 u3 = r1[lane + 96];
            a1 = (dot4(u0) + dot4(u1)) + (dot4(u2) + dot4(u3));
        }
        if (q2 < NQP) {   // s2 = s0+1..s0+3 >= 0 always
            const float4* r2 = reinterpret_cast<const float4*>(xb + (size_t)s2 * Hn) + k2 * 128;
            float4 u0 = r2[lane + 0];
            float4 u1 = r2[lane + 32];
            float4 u2 = r2[lane + 64];
            float4 u3 = r2[lane + 96];
            a2 = (dot4(u0) + dot4(u1)) + (dot4(u2) + dot4(u3));
        }
        a1 = warp_sum(a1);
        a2 = warp_sum(a2);
        if (lane == 0) {
            s_part[q1] = a1;
            if (q2 < NQP) s_part[q2] = a2;
        }
    }
    __syncthreads();
    if (tid < NPRO) {
        const int s = s0 - 3 + tid;
        float ssum = (s_part[tid * 4 + 0] + s_part[tid * 4 + 1]) +
                     (s_part[tid * 4 + 2] + s_part[tid * 4 + 3]);
        s_ir[tid] = (s >= 0) ? rsqrtf(ssum * (1.0f / (float)Hn) + EPSf) : 0.0f;
    }

    // Fold norm_weight into taps while the combine settles.
    t0.x *= nwv.x; t0.y *= nwv.x; t0.z *= nwv.x; t0.w *= nwv.x;
    t1.x *= nwv.y; t1.y *= nwv.y; t1.z *= nwv.y; t1.w *= nwv.y;
    t2.x *= nwv.z; t2.y *= nwv.z; t2.z *= nwv.z; t2.w *= nwv.z;
    t3.x *= nwv.w; t3.y *= nwv.w; t3.z *= nwv.w; t3.w *= nwv.w;
    __syncthreads();

    // ---- rolling window from halo rows (L2/DRAM read, once per block) ----
    float4 xm3, xm2, xm1;
    {
        float4 pre[3];
#pragma unroll
        for (int j = 0; j < 3; j++) {
            const int s = s0 - 3 + j;
            if (s >= 0) {
                float4 v = reinterpret_cast<const float4*>(xb + (size_t)s * Hn)[h4];
                const float r = s_ir[j];
                pre[j].x = v.x * r; pre[j].y = v.y * r; pre[j].z = v.z * r; pre[j].w = v.w * r;
            } else {
                pre[j] = make_float4(0.f, 0.f, 0.f, 0.f);
            }
        }
        xm3 = pre[0]; xm2 = pre[1]; xm1 = pre[2];
    }

    // ---- pipelined main loop: chunks of 4 rows ----
    const int jq = warp >> 2;            // my quarter's row within a chunk (0..3)
    const int kq = warp & 3;             // my quarter index (0..3)

#pragma unroll 1
    for (int c = 0; c < NCHK; c++) {
        // (1) issue next chunk's reduction loads: quarter of row s0+4(c+1)+jq
        float4 p0, p1, p2, p3;
        const bool more = (c + 1 < NCHK);
        if (more) {
            const int sn = s0 + 4 * (c + 1) + jq;
            const float4* rq = reinterpret_cast<const float4*>(xb + (size_t)sn * Hn) + kq * 128;
            p0 = rq[lane + 0];
            p1 = rq[lane + 32];
            p2 = rq[lane + 64];
            p3 = rq[lane + 96];
        }

        // (2) conv + store current chunk (rows s0+4c .. +3); loads above stay in flight
        const int sb = s0 + 4 * c;
#pragma unroll
        for (int j = 0; j < CHK; j++) {
            const int s = sb + j;
            float4 v = reinterpret_cast<const float4*>(xb + (size_t)s * Hn)[h4];
            const float r = s_ir[3 + 4 * c + j];
            float4 xn;
            xn.x = v.x * r; xn.y = v.y * r; xn.z = v.z * r; xn.w = v.w * r;

            float4 y;
            y.x = fmaf(t0.x, xm3.x, fmaf(t0.y, xm2.x, fmaf(t0.z, xm1.x, fmaf(t0.w, xn.x, bias.x))));
            y.y = fmaf(t1.x, xm3.y, fmaf(t1.y, xm2.y, fmaf(t1.z, xm1.y, fmaf(t1.w, xn.y, bias.y))));
            y.z = fmaf(t2.x, xm3.z, fmaf(t2.y, xm2.z, fmaf(t2.z, xm1.z, fmaf(t2.w, xn.z, bias.z))));
            y.w = fmaf(t3.x, xm3.w, fmaf(t3.y, xm2.w, fmaf(t3.z, xm1.w, fmaf(t3.w, xn.w, bias.w))));

            __stcs(reinterpret_cast<float4*>(ob + (size_t)s * Hn) + h4, y);

            xm3 = xm2; xm2 = xm1; xm1 = xn;
        }

        // (3) consume the loads into the reduction for chunk c+1
        if (more) {
            float a = (dot4(p0) + dot4(p1)) + (dot4(p2) + dot4(p3));
            a = warp_sum(a);
            if (lane == 0)
                s_part[warp] = a;
            __syncthreads();
            if (tid < CHK) {
                float ssum = (s_part[tid * 4 + 0] + s_part[tid * 4 + 1]) +
                             (s_part[tid * 4 + 2] + s_part[tid * 4 + 3]);
                s_ir[7 + 4 * c + tid] = rsqrtf(ssum * (1.0f / (float)Hn) + EPSf);
            }
            __syncthreads();
        }
    }
}

// ---------------------------------------------------------------------------
// Inputs (metadata order): hidden_states, norm_weight, conv_weight, conv_bias
// ---------------------------------------------------------------------------
extern "C" void kernel_launch(void* const* d_in, const int* in_sizes, int n_in,
                              void* d_out, int out_size) {
    const float* x  = (const float*)d_in[0];
    const float* nw = (const float*)d_in[1];
    const float* cw = (const float*)d_in[2];
    const float* cb = (const float*)d_in[3];
    float* out = (float*)d_out;

    dim3 grid(Sn / CS, Bn);             // (256, 4) = 1024 blocks
    fused_kernel<<<grid, 512>>>(x, nw, cw, cb, out);
}